// round 8
// baseline (speedup 1.0000x reference)
#include <cuda_runtime.h>

#define BATCH    8
#define NPOS     4096   // 64*64
#define KBITS    8
#define DV       32
#define NTILES   16
#define NBLOCKS  128
#define NTHREADS 256

// Scratch (allocation-free rule: __device__ globals)
__device__ unsigned char g_codes[BATCH * NPOS];
__device__ int           g_part[BATCH * NTILES * 256];
__device__ float         g_table[BATCH * 256 * DV];

// Software grid barrier state. Self-restoring across replays because the
// kernel executes an EVEN number of barriers (sense: 0 -> 1 -> 0).
__device__ unsigned          g_count;   // zero-initialized
__device__ volatile unsigned g_sense;   // zero-initialized

__device__ __forceinline__ void grid_barrier(unsigned* local_sense)
{
    __syncthreads();
    if (threadIdx.x == 0) {
        const unsigned s = *local_sense ^ 1u;
        *local_sense = s;
        __threadfence();                       // publish this block's phase data
        const unsigned pos = atomicAdd(&g_count, 1u);
        if (pos == NBLOCKS - 1) {
            g_count = 0;                       // reset for next barrier
            __threadfence();                   // order reset before release
            g_sense = s;                       // release
        } else {
            while (g_sense != s) { }           // spin (single-wave grid: safe)
        }
        __threadfence();                       // acquire
    }
    __syncthreads();
}

__global__ void __launch_bounds__(NTHREADS, 1)
k_fused(const float* __restrict__ z,
        const float* __restrict__ temp,
        const float* __restrict__ vemb,
        float* __restrict__ out)
{
    __shared__ int   hist[256];
    __shared__ float cnt_s[256];
    __shared__ float w_s[9];

    unsigned local_sense = 0;
    const int tid = threadIdx.x;
    const int bid = blockIdx.x;

    // ---------------- Phase 1: bitpack + per-block partial histogram -------
    hist[tid] = 0;
    __syncthreads();
    {
        const int b = bid >> 4;
        const int t = bid & (NTILES - 1);
        const int n = (t << 8) | tid;

        const float* zb = z + (size_t)b * KBITS * NPOS + n;
        int code = 0;
#pragma unroll
        for (int k = 0; k < KBITS; k++)
            code |= (zb[(size_t)k * NPOS] > 0.5f) ? (1 << k) : 0;

        g_codes[b * NPOS + n] = (unsigned char)code;
        atomicAdd(&hist[code], 1);
        __syncthreads();
        g_part[(b * NTILES + t) * 256 + tid] = hist[tid];
    }

    grid_barrier(&local_sense);

    // ---------------- Phase 2: normalized value table ----------------------
    // block (b, qgroup of 16); warp handles q = qbase+warp and qbase+warp+8.
    {
        const int b = bid >> 4;
        if (tid < 9) {
            const float t = fmaxf(*temp, 0.1f);
            w_s[tid] = expf(-(float)tid / t);
        }
        int cnt = 0;
#pragma unroll
        for (int t = 0; t < NTILES; t++)
            cnt += g_part[(b * NTILES + t) * 256 + tid];
        cnt_s[tid] = (float)cnt;
        __syncthreads();

        const int warp  = tid >> 5;
        const int lane  = tid & 31;
        const int qbase = (bid & 15) << 4;

#pragma unroll
        for (int qq = 0; qq < 2; qq++) {
            const int q = qbase + warp + (qq << 3);
            float acc  = 0.0f;
            float zsum = 0.0f;
#pragma unroll 8
            for (int c = 0; c < 256; c++) {
                const float wc = cnt_s[c] * w_s[__popc(q ^ c)];
                zsum += wc;
                acc  += wc * __ldg(vemb + c * DV + lane);
            }
            g_table[((b << 8) | q) * DV + lane] = acc / zsum;
        }
    }

    grid_barrier(&local_sense);

    // ---------------- Phase 3: scatter output ------------------------------
    // thread = (b, n-quad, dq); loops 8 consecutive d on the same codes.
    {
        const int t  = bid * NTHREADS + tid;   // 0 .. 32767
        const int b  = t >> 12;
        const int r  = t & 4095;
        const int n4 = r & 1023;
        const int dq = r >> 10;                // 0..3

        const uchar4 c = *(const uchar4*)(g_codes + b * NPOS + n4 * 4);
        const float* __restrict__ tb = g_table + (b << 13);      // b*256*32
        float* __restrict__ ob = out + (((size_t)b * DV) << 12) + n4 * 4;

#pragma unroll
        for (int i = 0; i < 8; i++) {
            const int d = (dq << 3) + i;
            float4 v;
            v.x = tb[c.x * DV + d];
            v.y = tb[c.y * DV + d];
            v.z = tb[c.z * DV + d];
            v.w = tb[c.w * DV + d];
            *(float4*)(ob + ((size_t)d << 12)) = v;
        }
    }
}

// ---------------------------------------------------------------------------
extern "C" void kernel_launch(void* const* d_in, const int* in_sizes, int n_in,
                              void* d_out, int out_size)
{
    const float* z    = (const float*)d_in[0];   // (8,8,64,64) f32
    const float* temp = (const float*)d_in[1];   // scalar f32
    const float* vemb = (const float*)d_in[2];   // (256,32) f32
    float*       out  = (float*)d_out;           // (8,32,64,64) f32

    k_fused<<<NBLOCKS, NTHREADS>>>(z, temp, vemb, out);
}

// round 11
// speedup vs baseline: 1.0013x; 1.0013x over previous
#include <cuda_runtime.h>

#define BATCH    8
#define NPOS     4096   // 64*64
#define KBITS    8
#define DV       32
#define NTILES   16     // blocks per batch
#define NBLOCKS  128    // BATCH * NTILES
#define NTHREADS 256

// Scratch (allocation-free rule: __device__ globals)
__device__ unsigned char g_codes[BATCH * NPOS];
__device__ int           g_part[BATCH * NTILES * 256];
__device__ float         g_table[BATCH * 256 * DV];

// Per-batch sense-reversal barriers (16 arrivals each). Self-restoring across
// graph replays: each launch executes an EVEN number of barriers per batch,
// so sense returns to 0 and count is reset by the last arriver.
__device__ unsigned          g_bcount[BATCH];   // zero-initialized
__device__ volatile unsigned g_bsense[BATCH];   // zero-initialized

__device__ __forceinline__ void batch_barrier(int b, unsigned* local_sense)
{
    __syncthreads();
    if (threadIdx.x == 0) {
        const unsigned s = *local_sense ^ 1u;
        *local_sense = s;
        __threadfence();                         // publish this block's data
        const unsigned pos = atomicAdd(&g_bcount[b], 1u);
        if (pos == NTILES - 1) {
            g_bcount[b] = 0;                     // reset for next barrier
            __threadfence();                     // order reset before release
            g_bsense[b] = s;                     // release
        } else {
            while (g_bsense[b] != s) { }         // spin (grid co-resident)
        }
        __threadfence();                         // acquire
    }
    __syncthreads();
}

__global__ void __launch_bounds__(NTHREADS, 1)
k_fused(const float* __restrict__ z,
        const float* __restrict__ temp,
        const float* __restrict__ vemb,
        float* __restrict__ out)
{
    __shared__ int   hist[256];
    __shared__ float cnt_s[256];
    __shared__ float w_s[9];

    unsigned local_sense = 0;
    const int tid = threadIdx.x;
    const int b   = blockIdx.x >> 4;            // batch
    const int t   = blockIdx.x & (NTILES - 1);  // tile within batch

    // ---------------- Phase 1: bitpack + per-tile partial histogram --------
    hist[tid] = 0;
    __syncthreads();
    {
        const int n = (t << 8) | tid;
        const float* zb = z + (size_t)b * KBITS * NPOS + n;
        int code = 0;
#pragma unroll
        for (int k = 0; k < KBITS; k++)
            code |= (zb[(size_t)k * NPOS] > 0.5f) ? (1 << k) : 0;

        g_codes[b * NPOS + n] = (unsigned char)code;
        atomicAdd(&hist[code], 1);
        __syncthreads();
        g_part[(b * NTILES + t) * 256 + tid] = hist[tid];
    }

    batch_barrier(b, &local_sense);

    // ---------------- Phase 2: normalized value table ----------------------
    // 16 blocks per batch; this block handles q in {qbase+warp, qbase+warp+8}.
    {
        if (tid < 9) {
            const float tt = fmaxf(*temp, 0.1f);
            w_s[tid] = expf(-(float)tid / tt);
        }
        int cnt = 0;
#pragma unroll
        for (int p = 0; p < NTILES; p++)
            cnt += g_part[(b * NTILES + p) * 256 + tid];
        cnt_s[tid] = (float)cnt;
        __syncthreads();

        const int warp  = tid >> 5;
        const int lane  = tid & 31;
        const int qbase = t << 4;

#pragma unroll
        for (int qq = 0; qq < 2; qq++) {
            const int q = qbase + warp + (qq << 3);
            float acc  = 0.0f;
            float zsum = 0.0f;
#pragma unroll 8
            for (int c = 0; c < 256; c++) {
                const float wc = cnt_s[c] * w_s[__popc(q ^ c)];
                zsum += wc;
                acc  += wc * __ldg(vemb + c * DV + lane);
            }
            g_table[((b << 8) | q) * DV + lane] = acc / zsum;
        }
    }

    batch_barrier(b, &local_sense);

    // ---------------- Phase 3: scatter output ------------------------------
    // 4096 threads per batch: thread = (dq, n-quad); 8 d x float4 stores.
    {
        const int lt = (t << 8) | tid;          // 0 .. 4095 within batch
        const int n4 = lt & 1023;
        const int dq = lt >> 10;                // 0..3

        const uchar4 c = *(const uchar4*)(g_codes + b * NPOS + n4 * 4);
        const float* __restrict__ tb = g_table + (b << 13);      // b*256*32
        float* __restrict__ ob = out + (((size_t)b * DV) << 12) + n4 * 4;

#pragma unroll
        for (int i = 0; i < 8; i++) {
            const int d = (dq << 3) + i;
            float4 v;
            v.x = tb[c.x * DV + d];
            v.y = tb[c.y * DV + d];
            v.z = tb[c.z * DV + d];
            v.w = tb[c.w * DV + d];
            *(float4*)(ob + ((size_t)d << 12)) = v;
        }
    }
}

// ---------------------------------------------------------------------------
extern "C" void kernel_launch(void* const* d_in, const int* in_sizes, int n_in,
                              void* d_out, int out_size)
{
    const float* z    = (const float*)d_in[0];   // (8,8,64,64) f32
    const float* temp = (const float*)d_in[1];   // scalar f32
    const float* vemb = (const float*)d_in[2];   // (256,32) f32
    float*       out  = (float*)d_out;           // (8,32,64,64) f32

    k_fused<<<NBLOCKS, NTHREADS>>>(z, temp, vemb, out);
}